// round 4
// baseline (speedup 1.0000x reference)
#include <cuda_runtime.h>
#include <cuda_bf16.h>

// Problem constants
#define B_ 8
#define T_ 2048
#define I_ 64
#define H_ 128
#define G3H 384                 // 3*H
#define TRI 2098176             // T*(T+1)/2
#define COUT_ELEMS (B_*T_*H_)   // 2097152
#define GRU_CHUNK 256           // steps per gru launch (8 launches)

// Scratch (allocation-free rule: __device__ globals)
__device__ float g_xw[B_*T_*G3H];   // input projections (B,T,3H)
__device__ float g_h [B_*T_*H_];    // GRU hidden states
__device__ float g_e [B_*T_];       // attention logits
__device__ float g_w [B_*T_];       // exp(e - max)
__device__ float g_D [B_*T_];       // cumsum of w
__device__ float g_S [B_*16*H_];    // per-chunk partial sums for c_out scan

// ---------------------------------------------------------------------------
// f32x2 packed-FMA helpers (Blackwell; 2 fp32 FMAs per instruction per lane)
// ---------------------------------------------------------------------------
__device__ __forceinline__ void fma2(unsigned long long& acc,
                                     unsigned long long a,
                                     unsigned long long b) {
    asm("fma.rn.f32x2 %0, %1, %2, %0;" : "+l"(acc) : "l"(a), "l"(b));
}
__device__ __forceinline__ float pairsum(unsigned long long v) {
    float lo, hi;
    asm("mov.b64 {%0,%1}, %2;" : "=f"(lo), "=f"(hi) : "l"(v));
    return lo + hi;
}
__device__ __forceinline__ float sigmoidf_(float x) {
    return 1.0f / (1.0f + __expf(-x));
}

// ---------------------------------------------------------------------------
// 1) Input projection: xw[bt, j] = sum_k x[bt,k] * W_ih[j,k] + b_ih[j]
// ---------------------------------------------------------------------------
__global__ __launch_bounds__(384, 1)
void proj_kernel(const float* __restrict__ x,
                 const float* __restrict__ W_ih,
                 const float* __restrict__ b_ih) {
    const int row = threadIdx.x;          // 0..383
    const int bt0 = blockIdx.x * 64;
    __shared__ __align__(16) float xs[64 * I_];

    unsigned long long w[32];             // 64 floats of W_ih row
    const unsigned long long* wr =
        reinterpret_cast<const unsigned long long*>(W_ih + row * I_);
#pragma unroll
    for (int k = 0; k < 32; k++) w[k] = wr[k];
    const float bi = b_ih[row];

    const float4* xg = reinterpret_cast<const float4*>(x + (size_t)bt0 * I_);
    for (int i = threadIdx.x; i < 64 * I_ / 4; i += 384)
        reinterpret_cast<float4*>(xs)[i] = xg[i];
    __syncthreads();

    for (int j = 0; j < 64; j++) {
        unsigned long long a0 = 0ull, a1 = 0ull;
        const ulonglong2* hp = reinterpret_cast<const ulonglong2*>(xs + j * I_);
#pragma unroll
        for (int k = 0; k < 16; k++) {
            ulonglong2 hv = hp[k];
            fma2(a0, w[2 * k], hv.x);
            fma2(a1, w[2 * k + 1], hv.y);
        }
        g_xw[(size_t)(bt0 + j) * G3H + row] = pairsum(a0) + pairsum(a1) + bi;
    }
}

// ---------------------------------------------------------------------------
// 2) GRU recurrence chunk [t0, t0+GRU_CHUNK). One CTA per batch, 384 threads,
//    W_hh row in registers, 4 independent f32x2 accumulator chains.
//    Split into 8 sequential launches so ncu's skip-window lands on one.
// ---------------------------------------------------------------------------
__global__ __launch_bounds__(384, 1)
void gru_chunk_kernel(const float* __restrict__ W_hh,
                      const float* __restrict__ b_hh,
                      const int t0) {
    const int b = blockIdx.x;
    const int row = threadIdx.x;          // r: 0-127, z: 128-255, n: 256-383
    __shared__ __align__(16) float h_sh[H_];
    __shared__ float r_sh[H_];
    __shared__ float z_sh[H_];

    unsigned long long w[64];             // 128 floats of W_hh row
    const unsigned long long* wr =
        reinterpret_cast<const unsigned long long*>(W_hh + row * H_);
#pragma unroll
    for (int k = 0; k < 64; k++) w[k] = wr[k];
    const float bh = b_hh[row];

    // restore carried state
    float h_reg = 0.0f;
    if (t0 == 0) {
        if (row < H_) h_sh[row] = 0.0f;
    } else {
        const float* hprev = g_h + ((size_t)b * T_ + (t0 - 1)) * H_;
        if (row < H_) h_sh[row] = hprev[row];
        if (row >= 2 * H_) h_reg = hprev[row - 2 * H_];
    }

    const float* xwb = g_xw + (size_t)b * T_ * G3H;
    float xval_next = __ldg(xwb + (size_t)t0 * G3H + row);   // prefetch first
    __syncthreads();

    for (int t = t0; t < t0 + GRU_CHUNK; t++) {
        const float xval = xval_next;
        // branchless prefetch (clamped; value unused on last iter)
        const int tn = (t + 1 < T_) ? (t + 1) : t;
        xval_next = __ldg(xwb + (size_t)tn * G3H + row);

        unsigned long long a0 = 0ull, a1 = 0ull, a2 = 0ull, a3 = 0ull;
        const ulonglong2* hp = reinterpret_cast<const ulonglong2*>(h_sh);
#pragma unroll
        for (int k = 0; k < 16; k++) {
            ulonglong2 hv0 = hp[2 * k];
            ulonglong2 hv1 = hp[2 * k + 1];
            fma2(a0, w[4 * k + 0], hv0.x);
            fma2(a1, w[4 * k + 1], hv0.y);
            fma2(a2, w[4 * k + 2], hv1.x);
            fma2(a3, w[4 * k + 3], hv1.y);
        }
        const float dot = (pairsum(a0) + pairsum(a1)) +
                          (pairsum(a2) + pairsum(a3)) + bh;   // hw + b_hh

        if (row < H_) {
            r_sh[row] = sigmoidf_(xval + dot);
        } else if (row < 2 * H_) {
            z_sh[row - H_] = sigmoidf_(xval + dot);
        }
        __syncthreads();   // r,z ready; all h_sh reads done

        if (row >= 2 * H_) {
            const int i = row - 2 * H_;
            const float n = tanhf(fmaf(r_sh[i], dot, xval));
            const float z = z_sh[i];
            const float hn = (1.0f - z) * n + z * h_reg;
            h_reg = hn;
            h_sh[i] = hn;
            g_h[((size_t)b * T_ + t) * H_ + i] = hn;
        }
        __syncthreads();   // h_sh updated before next step's dots
    }
}

// ---------------------------------------------------------------------------
// 3) e[bt] = dot(h[bt,:], W_lin) + b_lin   (one warp per bt)
// ---------------------------------------------------------------------------
__global__ __launch_bounds__(128)
void e_kernel(const float* __restrict__ W_lin,
              const float* __restrict__ b_lin) {
    const int bt = blockIdx.x * 4 + (threadIdx.x >> 5);
    const int lane = threadIdx.x & 31;
    float4 hv = reinterpret_cast<const float4*>(g_h + (size_t)bt * H_)[lane];
    float4 wv = reinterpret_cast<const float4*>(W_lin)[lane];
    float s = hv.x * wv.x + hv.y * wv.y + hv.z * wv.z + hv.w * wv.w;
#pragma unroll
    for (int o = 16; o; o >>= 1) s += __shfl_xor_sync(0xffffffffu, s, o);
    if (lane == 0) g_e[bt] = s + b_lin[0];
}

// ---------------------------------------------------------------------------
// 4) Per batch: M = max(e), w = exp(e-M), D = inclusive cumsum(w)
// ---------------------------------------------------------------------------
__global__ __launch_bounds__(512, 1)
void scan_kernel() {
    const int b = blockIdx.x;
    const int tid = threadIdx.x;
    __shared__ float sh[512];

    const float* eb = g_e + b * T_;
    float4 ev = reinterpret_cast<const float4*>(eb)[tid];

    float m = fmaxf(fmaxf(ev.x, ev.y), fmaxf(ev.z, ev.w));
    sh[tid] = m;
    __syncthreads();
#pragma unroll
    for (int o = 256; o; o >>= 1) {
        if (tid < o) sh[tid] = fmaxf(sh[tid], sh[tid + o]);
        __syncthreads();
    }
    const float M = sh[0];
    __syncthreads();

    const float w0 = __expf(ev.x - M);
    const float w1 = __expf(ev.y - M);
    const float w2 = __expf(ev.z - M);
    const float w3 = __expf(ev.w - M);
    const float p0 = w0, p1 = p0 + w1, p2 = p1 + w2, p3 = p2 + w3;

    sh[tid] = p3;
    __syncthreads();
    for (int o = 1; o < 512; o <<= 1) {     // Hillis-Steele inclusive scan
        float v = (tid >= o) ? sh[tid - o] : 0.0f;
        __syncthreads();
        sh[tid] += v;
        __syncthreads();
    }
    const float base = sh[tid] - p3;        // exclusive prefix of this thread

    reinterpret_cast<float4*>(g_w + b * T_)[tid] = make_float4(w0, w1, w2, w3);
    reinterpret_cast<float4*>(g_D + b * T_)[tid] =
        make_float4(base + p0, base + p1, base + p2, base + p3);
}

// ---------------------------------------------------------------------------
// 5) c_out prefix scan, 2-pass chunked (16 chunks of 128 steps per batch)
// ---------------------------------------------------------------------------
__global__ __launch_bounds__(128)
void cout_partial_kernel() {
    const int c = blockIdx.x, b = blockIdx.y, tid = threadIdx.x;
    const float* wb = g_w + b * T_;
    float acc = 0.0f;
    for (int t = c * 128; t < c * 128 + 128; t++)
        acc = fmaf(__ldg(wb + t), __ldg(&g_h[((size_t)b * T_ + t) * H_ + tid]), acc);
    g_S[(b * 16 + c) * H_ + tid] = acc;
}

__global__ __launch_bounds__(128)
void cout_main_kernel(float* __restrict__ out) {
    const int c = blockIdx.x, b = blockIdx.y, tid = threadIdx.x;
    float acc = 0.0f;
    for (int c2 = 0; c2 < c; c2++) acc += g_S[(b * 16 + c2) * H_ + tid];
    const float* wb = g_w + b * T_;
    const float* Db = g_D + b * T_;
    for (int t = c * 128; t < c * 128 + 128; t++) {
        acc = fmaf(__ldg(wb + t), __ldg(&g_h[((size_t)b * T_ + t) * H_ + tid]), acc);
        out[((size_t)b * T_ + t) * H_ + tid] = acc * (1.0f / __ldg(Db + t));
    }
}

// ---------------------------------------------------------------------------
// 6) alpha_out[b, t(t+1)/2 + s] = w[b,s] / D[b,t],  s = 0..t
// ---------------------------------------------------------------------------
__global__ __launch_bounds__(256)
void alpha_kernel(float* __restrict__ out) {
    const int t = blockIdx.x, b = blockIdx.y;
    const float invD = 1.0f / g_D[b * T_ + t];
    const float* wb = g_w + b * T_;
    float* dst = out + COUT_ELEMS + (size_t)b * TRI + ((size_t)t * (t + 1)) / 2;
    for (int s = threadIdx.x; s <= t; s += 256)
        dst[s] = wb[s] * invD;
}

// ---------------------------------------------------------------------------
extern "C" void kernel_launch(void* const* d_in, const int* in_sizes, int n_in,
                              void* d_out, int out_size) {
    const float* x     = (const float*)d_in[0];
    const float* W_ih  = (const float*)d_in[1];
    const float* W_hh  = (const float*)d_in[2];
    const float* b_ih  = (const float*)d_in[3];
    const float* b_hh  = (const float*)d_in[4];
    const float* W_lin = (const float*)d_in[5];
    const float* b_lin = (const float*)d_in[6];
    float* out = (float*)d_out;

    proj_kernel<<<256, 384>>>(x, W_ih, b_ih);
    // 8 sequential GRU chunk launches (positions 1..8 in the graph) so the
    // ncu skip-window necessarily captures one of them.
    for (int t0 = 0; t0 < T_; t0 += GRU_CHUNK)
        gru_chunk_kernel<<<B_, 384>>>(W_hh, b_hh, t0);
    e_kernel<<<(B_ * T_) / 4, 128>>>(W_lin, b_lin);
    scan_kernel<<<B_, 512>>>();
    cout_partial_kernel<<<dim3(16, B_), 128>>>();
    cout_main_kernel<<<dim3(16, B_), 128>>>(out);
    alpha_kernel<<<dim3(T_, B_), 256>>>(out);
}

// round 5
// speedup vs baseline: 1.0779x; 1.0779x over previous
#include <cuda_runtime.h>
#include <cuda_bf16.h>

// Problem constants
#define B_ 8
#define T_ 2048
#define I_ 64
#define H_ 128
#define G3H 384                 // 3*H
#define TRI 2098176             // T*(T+1)/2
#define COUT_ELEMS (B_*T_*H_)   // 2097152

// Scratch (allocation-free rule: __device__ globals)
__device__ float g_xw[B_*T_*G3H];   // input projections (B,T,3H)
__device__ float g_h [B_*T_*H_];    // GRU hidden states
__device__ float g_e [B_*T_];       // attention logits
__device__ float g_w [B_*T_];       // exp(e - max)
__device__ float g_D [B_*T_];       // cumsum of w
__device__ float g_S [B_*16*H_];    // per-chunk partial sums for c_out scan

// ---------------------------------------------------------------------------
// f32x2 packed-FMA helpers (Blackwell; 2 fp32 FMAs per instruction per lane)
// ---------------------------------------------------------------------------
__device__ __forceinline__ void fma2(unsigned long long& acc,
                                     unsigned long long a,
                                     unsigned long long b) {
    asm("fma.rn.f32x2 %0, %1, %2, %0;" : "+l"(acc) : "l"(a), "l"(b));
}
__device__ __forceinline__ float pairsum(unsigned long long v) {
    float lo, hi;
    asm("mov.b64 {%0,%1}, %2;" : "=f"(lo), "=f"(hi) : "l"(v));
    return lo + hi;
}

// Fast activations: MUFU EX2 + MUFU RCP only (no IEEE div, no libdevice
// branches). ~2 ULP; saturate correctly at +/-inf.
#define LOG2E 1.4426950408889634f
__device__ __forceinline__ float fast_sigmoid(float x) {
    float e, d, r;
    asm("ex2.approx.f32 %0, %1;" : "=f"(e) : "f"(-LOG2E * x));   // e = 2^(-x*log2e) = exp(-x)
    d = e + 1.0f;
    asm("rcp.approx.f32 %0, %1;" : "=f"(r) : "f"(d));
    return r;                                                     // 1/(1+exp(-x))
}
__device__ __forceinline__ float fast_tanh(float x) {
    float e, d, r;
    asm("ex2.approx.f32 %0, %1;" : "=f"(e) : "f"((2.0f * LOG2E) * x));  // exp(2x)
    d = e + 1.0f;
    asm("rcp.approx.f32 %0, %1;" : "=f"(r) : "f"(d));
    return fmaf(-2.0f, r, 1.0f);                                  // 1 - 2/(1+exp(2x))
}

// ---------------------------------------------------------------------------
// 1) Input projection: xw[bt, j] = sum_k x[bt,k] * W_ih[j,k] + b_ih[j]
// ---------------------------------------------------------------------------
__global__ __launch_bounds__(384, 1)
void proj_kernel(const float* __restrict__ x,
                 const float* __restrict__ W_ih,
                 const float* __restrict__ b_ih) {
    const int row = threadIdx.x;          // 0..383
    const int bt0 = blockIdx.x * 64;
    __shared__ __align__(16) float xs[64 * I_];

    unsigned long long w[32];             // 64 floats of W_ih row
    const unsigned long long* wr =
        reinterpret_cast<const unsigned long long*>(W_ih + row * I_);
#pragma unroll
    for (int k = 0; k < 32; k++) w[k] = wr[k];
    const float bi = b_ih[row];

    const float4* xg = reinterpret_cast<const float4*>(x + (size_t)bt0 * I_);
    for (int i = threadIdx.x; i < 64 * I_ / 4; i += 384)
        reinterpret_cast<float4*>(xs)[i] = xg[i];
    __syncthreads();

    for (int j = 0; j < 64; j++) {
        unsigned long long a0 = 0ull, a1 = 0ull;
        const ulonglong2* hp = reinterpret_cast<const ulonglong2*>(xs + j * I_);
#pragma unroll
        for (int k = 0; k < 16; k++) {
            ulonglong2 hv = hp[k];
            fma2(a0, w[2 * k], hv.x);
            fma2(a1, w[2 * k + 1], hv.y);
        }
        g_xw[(size_t)(bt0 + j) * G3H + row] = pairsum(a0) + pairsum(a1) + bi;
    }
}

// ---------------------------------------------------------------------------
// 2) GRU recurrence (monolithic). One CTA per batch, 384 threads, W_hh row in
//    registers, 4 independent f32x2 chains, fast MUFU activations, branchless
//    interleaved r/z exchange.
// ---------------------------------------------------------------------------
__global__ __launch_bounds__(384, 1)
void gru_kernel(const float* __restrict__ W_hh,
                const float* __restrict__ b_hh) {
    const int b = blockIdx.x;
    const int row = threadIdx.x;          // r: 0-127, z: 128-255, n: 256-383
    __shared__ __align__(16) float h_sh[H_];
    __shared__ __align__(8) float rz_sh[2 * H_];   // interleaved [r0,z0,r1,z1,...]

    unsigned long long w[64];             // 128 floats of W_hh row
    const unsigned long long* wr =
        reinterpret_cast<const unsigned long long*>(W_hh + row * H_);
#pragma unroll
    for (int k = 0; k < 64; k++) w[k] = wr[k];
    const float bh = b_hh[row];

    // branchless destination for the r/z exchange (valid for row < 256)
    const int rz_idx = ((row & 127) << 1) | ((row >> 7) & 1);

    if (row < H_) h_sh[row] = 0.0f;
    float h_reg = 0.0f;                   // n-threads own h[row-256]

    const float* xp = g_xw + (size_t)b * T_ * G3H + row;
    float xval_next = __ldg(xp);          // prefetch t=0
    __syncthreads();

#pragma unroll 2
    for (int t = 0; t < T_; t++) {
        const float xval = xval_next;
        xp += G3H;
        xval_next = __ldg(xp);            // prefetch next (last iter reads
                                          // one row past: within g_h region?
                                          // no — clamp below)
        // NOTE: on the final iteration this reads g_xw[b*T*G3H + T*G3H + row],
        // which for b == B_-1 would be out of bounds of g_xw. Guard:
        // (branch is uniform & predictable; cost ~1 cyc)
        // -- implemented by clamping the pointer on the last step:
        if (t == T_ - 1) xval_next = 0.0f;  // dead value, avoid OOB read
        // (the compiler keeps the prefetch speculative for t < T_-1)

        unsigned long long a0 = 0ull, a1 = 0ull, a2 = 0ull, a3 = 0ull;
        const ulonglong2* hp = reinterpret_cast<const ulonglong2*>(h_sh);
#pragma unroll
        for (int k = 0; k < 16; k++) {
            ulonglong2 hv0 = hp[2 * k];
            ulonglong2 hv1 = hp[2 * k + 1];
            fma2(a0, w[4 * k + 0], hv0.x);
            fma2(a1, w[4 * k + 1], hv0.y);
            fma2(a2, w[4 * k + 2], hv1.x);
            fma2(a3, w[4 * k + 3], hv1.y);
        }
        const float dot = (pairsum(a0) + pairsum(a1)) +
                          (pairsum(a2) + pairsum(a3)) + bh;   // hw + b_hh

        if (row < 2 * H_) {
            rz_sh[rz_idx] = fast_sigmoid(xval + dot);
        }
        __syncthreads();   // rz ready; all h_sh reads done

        if (row >= 2 * H_) {
            const int i = row - 2 * H_;
            const float2 rz = *reinterpret_cast<const float2*>(&rz_sh[2 * i]);
            const float n = fast_tanh(fmaf(rz.x, dot, xval));
            const float z = rz.y;
            const float hn = fmaf(z, h_reg - n, n);   // (1-z)n + z h
            h_reg = hn;
            h_sh[i] = hn;
            g_h[((size_t)b * T_ + t) * H_ + i] = hn;
        }
        __syncthreads();   // h_sh updated before next step's dots
    }
}

// ---------------------------------------------------------------------------
// 3) e[bt] = dot(h[bt,:], W_lin) + b_lin   (one warp per bt)
// ---------------------------------------------------------------------------
__global__ __launch_bounds__(128)
void e_kernel(const float* __restrict__ W_lin,
              const float* __restrict__ b_lin) {
    const int bt = blockIdx.x * 4 + (threadIdx.x >> 5);
    const int lane = threadIdx.x & 31;
    float4 hv = reinterpret_cast<const float4*>(g_h + (size_t)bt * H_)[lane];
    float4 wv = reinterpret_cast<const float4*>(W_lin)[lane];
    float s = hv.x * wv.x + hv.y * wv.y + hv.z * wv.z + hv.w * wv.w;
#pragma unroll
    for (int o = 16; o; o >>= 1) s += __shfl_xor_sync(0xffffffffu, s, o);
    if (lane == 0) g_e[bt] = s + b_lin[0];
}

// ---------------------------------------------------------------------------
// 4) Per batch: M = max(e), w = exp(e-M), D = inclusive cumsum(w)
// ---------------------------------------------------------------------------
__global__ __launch_bounds__(512, 1)
void scan_kernel() {
    const int b = blockIdx.x;
    const int tid = threadIdx.x;
    __shared__ float sh[512];

    const float* eb = g_e + b * T_;
    float4 ev = reinterpret_cast<const float4*>(eb)[tid];

    float m = fmaxf(fmaxf(ev.x, ev.y), fmaxf(ev.z, ev.w));
    sh[tid] = m;
    __syncthreads();
#pragma unroll
    for (int o = 256; o; o >>= 1) {
        if (tid < o) sh[tid] = fmaxf(sh[tid], sh[tid + o]);
        __syncthreads();
    }
    const float M = sh[0];
    __syncthreads();

    const float w0 = __expf(ev.x - M);
    const float w1 = __expf(ev.y - M);
    const float w2 = __expf(ev.z - M);
    const float w3 = __expf(ev.w - M);
    const float p0 = w0, p1 = p0 + w1, p2 = p1 + w2, p3 = p2 + w3;

    sh[tid] = p3;
    __syncthreads();
    for (int o = 1; o < 512; o <<= 1) {     // Hillis-Steele inclusive scan
        float v = (tid >= o) ? sh[tid - o] : 0.0f;
        __syncthreads();
        sh[tid] += v;
        __syncthreads();
    }
    const float base = sh[tid] - p3;        // exclusive prefix of this thread

    reinterpret_cast<float4*>(g_w + b * T_)[tid] = make_float4(w0, w1, w2, w3);
    reinterpret_cast<float4*>(g_D + b * T_)[tid] =
        make_float4(base + p0, base + p1, base + p2, base + p3);
}

// ---------------------------------------------------------------------------
// 5) c_out prefix scan, 2-pass chunked (16 chunks of 128 steps per batch)
// ---------------------------------------------------------------------------
__global__ __launch_bounds__(128)
void cout_partial_kernel() {
    const int c = blockIdx.x, b = blockIdx.y, tid = threadIdx.x;
    const float* wb = g_w + b * T_;
    float acc = 0.0f;
    for (int t = c * 128; t < c * 128 + 128; t++)
        acc = fmaf(__ldg(wb + t), __ldg(&g_h[((size_t)b * T_ + t) * H_ + tid]), acc);
    g_S[(b * 16 + c) * H_ + tid] = acc;
}

__global__ __launch_bounds__(128)
void cout_main_kernel(float* __restrict__ out) {
    const int c = blockIdx.x, b = blockIdx.y, tid = threadIdx.x;
    float acc = 0.0f;
    for (int c2 = 0; c2 < c; c2++) acc += g_S[(b * 16 + c2) * H_ + tid];
    const float* wb = g_w + b * T_;
    const float* Db = g_D + b * T_;
    for (int t = c * 128; t < c * 128 + 128; t++) {
        acc = fmaf(__ldg(wb + t), __ldg(&g_h[((size_t)b * T_ + t) * H_ + tid]), acc);
        out[((size_t)b * T_ + t) * H_ + tid] = acc * (1.0f / __ldg(Db + t));
    }
}

// ---------------------------------------------------------------------------
// 6) alpha_out[b, t(t+1)/2 + s] = w[b,s] / D[b,t],  s = 0..t
// ---------------------------------------------------------------------------
__global__ __launch_bounds__(256)
void alpha_kernel(float* __restrict__ out) {
    const int t = blockIdx.x, b = blockIdx.y;
    const float invD = 1.0f / g_D[b * T_ + t];
    const float* wb = g_w + b * T_;
    float* dst = out + COUT_ELEMS + (size_t)b * TRI + ((size_t)t * (t + 1)) / 2;
    for (int s = threadIdx.x; s <= t; s += 256)
        dst[s] = wb[s] * invD;
}

// ---------------------------------------------------------------------------
extern "C" void kernel_launch(void* const* d_in, const int* in_sizes, int n_in,
                              void* d_out, int out_size) {
    const float* x     = (const float*)d_in[0];
    const float* W_ih  = (const float*)d_in[1];
    const float* W_hh  = (const float*)d_in[2];
    const float* b_ih  = (const float*)d_in[3];
    const float* b_hh  = (const float*)d_in[4];
    const float* W_lin = (const float*)d_in[5];
    const float* b_lin = (const float*)d_in[6];
    float* out = (float*)d_out;

    proj_kernel<<<256, 384>>>(x, W_ih, b_ih);
    gru_kernel<<<B_, 384>>>(W_hh, b_hh);
    e_kernel<<<(B_ * T_) / 4, 128>>>(W_lin, b_lin);
    scan_kernel<<<B_, 512>>>();
    cout_partial_kernel<<<dim3(16, B_), 128>>>();
    cout_main_kernel<<<dim3(16, B_), 128>>>(out);
    alpha_kernel<<<dim3(T_, B_), 256>>>(out);
}

// round 8
// speedup vs baseline: 1.0889x; 1.0102x over previous
#include <cuda_runtime.h>
#include <cuda_bf16.h>

// Problem constants
#define B_ 8
#define T_ 2048
#define I_ 64
#define H_ 128
#define G3H 384                 // 3*H
#define TRI 2098176             // T*(T+1)/2
#define COUT_ELEMS (B_*T_*H_)   // 2097152

// Scratch (allocation-free rule: __device__ globals)
__device__ float g_xw[B_*T_*G3H];   // input projections (B,T,3H)
__device__ float g_h [B_*T_*H_];    // GRU hidden states
__device__ float g_e [B_*T_];       // attention logits
__device__ float g_w [B_*T_];       // exp(e - max)
__device__ float g_D [B_*T_];       // cumsum of w
__device__ float g_S [B_*16*H_];    // per-chunk partial sums for c_out scan

// ---------------------------------------------------------------------------
// f32x2 packed-FMA helpers (Blackwell; 2 fp32 FMAs per instruction per lane)
// ---------------------------------------------------------------------------
__device__ __forceinline__ void fma2(unsigned long long& acc,
                                     unsigned long long a,
                                     unsigned long long b) {
    asm("fma.rn.f32x2 %0, %1, %2, %0;" : "+l"(acc) : "l"(a), "l"(b));
}
__device__ __forceinline__ float pairsum(unsigned long long v) {
    float lo, hi;
    asm("mov.b64 {%0,%1}, %2;" : "=f"(lo), "=f"(hi) : "l"(v));
    return lo + hi;
}

// Fast activations: MUFU EX2 + MUFU RCP only (~2 ULP, proven 5e-7 end-to-end)
#define LOG2E 1.4426950408889634f
__device__ __forceinline__ float fast_sigmoid(float x) {
    float e, r;
    asm("ex2.approx.f32 %0, %1;" : "=f"(e) : "f"(-LOG2E * x));    // exp(-x)
    asm("rcp.approx.f32 %0, %1;" : "=f"(r) : "f"(e + 1.0f));
    return r;
}
__device__ __forceinline__ float fast_tanh(float x) {
    float e, r;
    asm("ex2.approx.f32 %0, %1;" : "=f"(e) : "f"((2.0f * LOG2E) * x));  // exp(2x)
    asm("rcp.approx.f32 %0, %1;" : "=f"(r) : "f"(e + 1.0f));
    return fmaf(-2.0f, r, 1.0f);
}

// ---------------------------------------------------------------------------
// 0) Dummy kernel: occupies a launch slot so ncu's skip-window lands on gru.
// ---------------------------------------------------------------------------
__global__ void dummy_kernel() {}

// ---------------------------------------------------------------------------
// 1) Input projection: xw[bt, j] = sum_k x[bt,k] * W_ih[j,k] + b_ih[j]
// ---------------------------------------------------------------------------
__global__ __launch_bounds__(384, 1)
void proj_kernel(const float* __restrict__ x,
                 const float* __restrict__ W_ih,
                 const float* __restrict__ b_ih) {
    const int row = threadIdx.x;          // 0..383
    const int bt0 = blockIdx.x * 64;
    __shared__ __align__(16) float xs[64 * I_];

    unsigned long long w[32];             // 64 floats of W_ih row
    const unsigned long long* wr =
        reinterpret_cast<const unsigned long long*>(W_ih + row * I_);
#pragma unroll
    for (int k = 0; k < 32; k++) w[k] = wr[k];
    const float bi = b_ih[row];

    const float4* xg = reinterpret_cast<const float4*>(x + (size_t)bt0 * I_);
    for (int i = threadIdx.x; i < 64 * I_ / 4; i += 384)
        reinterpret_cast<float4*>(xs)[i] = xg[i];
    __syncthreads();

    for (int j = 0; j < 64; j++) {
        unsigned long long a0 = 0ull, a1 = 0ull;
        const ulonglong2* hp = reinterpret_cast<const ulonglong2*>(xs + j * I_);
#pragma unroll
        for (int k = 0; k < 16; k++) {
            ulonglong2 hv = hp[k];
            fma2(a0, w[2 * k], hv.x);
            fma2(a1, w[2 * k + 1], hv.y);
        }
        g_xw[(size_t)(bt0 + j) * G3H + row] = pairsum(a0) + pairsum(a1) + bi;
    }
}

// ---------------------------------------------------------------------------
// 2) GRU recurrence chunk [t0, t1). One CTA per batch, 384 threads, W_hh row
//    in registers. Dot loop: two bursts of 16 front-batched LDS.128 feeding
//    32 FMA2 each (kills short-scoreboard interleave stalls).
// ---------------------------------------------------------------------------
__global__ __launch_bounds__(384, 1)
void gru_chunk_kernel(const float* __restrict__ W_hh,
                      const float* __restrict__ b_hh,
                      const int t0, const int t1) {
    const int b = blockIdx.x;
    const int row = threadIdx.x;          // r: 0-127, z: 128-255, n: 256-383
    __shared__ __align__(16) float h_sh[H_];
    __shared__ __align__(8) float rz_sh[2 * H_];   // interleaved [r0,z0,...]

    unsigned long long w[64];             // 128 floats of W_hh row
    const unsigned long long* wr =
        reinterpret_cast<const unsigned long long*>(W_hh + row * H_);
#pragma unroll
    for (int k = 0; k < 64; k++) w[k] = wr[k];
    const float bh = b_hh[row];

    const int rz_idx = ((row & 127) << 1) | ((row >> 7) & 1);

    // restore carried state
    float h_reg = 0.0f;
    if (t0 == 0) {
        if (row < H_) h_sh[row] = 0.0f;
    } else {
        const float* hprev = g_h + ((size_t)b * T_ + (t0 - 1)) * H_;
        if (row < H_) h_sh[row] = hprev[row];
        if (row >= 2 * H_) h_reg = hprev[row - 2 * H_];
    }

    const float* xp = g_xw + (size_t)b * T_ * G3H + (size_t)t0 * G3H + row;
    float xval_next = __ldg(xp);          // prefetch first step
    __syncthreads();

    for (int t = t0; t < t1; t++) {
        const float xval = xval_next;
        xp += (t < T_ - 1) ? G3H : 0;     // clamped (SEL, no branch, no OOB)
        xval_next = __ldg(xp);

        unsigned long long a0 = 0ull, a1 = 0ull, a2 = 0ull, a3 = 0ull;
        const ulonglong2* hp = reinterpret_cast<const ulonglong2*>(h_sh);
#pragma unroll
        for (int half = 0; half < 2; half++) {
            ulonglong2 hc[16];            // burst: 16x LDS.128 (MLP=16)
#pragma unroll
            for (int k = 0; k < 16; k++) hc[k] = hp[half * 16 + k];
#pragma unroll
            for (int k = 0; k < 16; k++) {
                const int kk = half * 16 + k;
                if (k & 1) {
                    fma2(a2, w[2 * kk], hc[k].x);
                    fma2(a3, w[2 * kk + 1], hc[k].y);
                } else {
                    fma2(a0, w[2 * kk], hc[k].x);
                    fma2(a1, w[2 * kk + 1], hc[k].y);
                }
            }
        }
        const float dot = (pairsum(a0) + pairsum(a1)) +
                          (pairsum(a2) + pairsum(a3)) + bh;   // hw + b_hh

        if (row < 2 * H_) {
            rz_sh[rz_idx] = fast_sigmoid(xval + dot);
        }
        __syncthreads();   // rz ready; all h_sh reads done

        if (row >= 2 * H_) {
            const int i = row - 2 * H_;
            const float2 rz = *reinterpret_cast<const float2*>(&rz_sh[2 * i]);
            const float n = fast_tanh(fmaf(rz.x, dot, xval));
            const float hn = fmaf(rz.y, h_reg - n, n);   // (1-z)n + z h
            h_reg = hn;
            h_sh[i] = hn;
            g_h[((size_t)b * T_ + t) * H_ + i] = hn;
        }
        __syncthreads();   // h_sh updated before next step's dots
    }
}

// ---------------------------------------------------------------------------
// 3) e[bt] = dot(h[bt,:], W_lin) + b_lin   (one warp per bt)
// ---------------------------------------------------------------------------
__global__ __launch_bounds__(128)
void e_kernel(const float* __restrict__ W_lin,
              const float* __restrict__ b_lin) {
    const int bt = blockIdx.x * 4 + (threadIdx.x >> 5);
    const int lane = threadIdx.x & 31;
    float4 hv = reinterpret_cast<const float4*>(g_h + (size_t)bt * H_)[lane];
    float4 wv = reinterpret_cast<const float4*>(W_lin)[lane];
    float s = hv.x * wv.x + hv.y * wv.y + hv.z * wv.z + hv.w * wv.w;
#pragma unroll
    for (int o = 16; o; o >>= 1) s += __shfl_xor_sync(0xffffffffu, s, o);
    if (lane == 0) g_e[bt] = s + b_lin[0];
}

// ---------------------------------------------------------------------------
// 4) Per batch: M = max(e), w = exp(e-M), D = inclusive cumsum(w)
// ---------------------------------------------------------------------------
__global__ __launch_bounds__(512, 1)
void scan_kernel() {
    const int b = blockIdx.x;
    const int tid = threadIdx.x;
    __shared__ float sh[512];

    const float* eb = g_e + b * T_;
    float4 ev = reinterpret_cast<const float4*>(eb)[tid];

    float m = fmaxf(fmaxf(ev.x, ev.y), fmaxf(ev.z, ev.w));
    sh[tid] = m;
    __syncthreads();
#pragma unroll
    for (int o = 256; o; o >>= 1) {
        if (tid < o) sh[tid] = fmaxf(sh[tid], sh[tid + o]);
        __syncthreads();
    }
    const float M = sh[0];
    __syncthreads();

    const float w0 = __expf(ev.x - M);
    const float w1 = __expf(ev.y - M);
    const float w2 = __expf(ev.z - M);
    const float w3 = __expf(ev.w - M);
    const float p0 = w0, p1 = p0 + w1, p2 = p1 + w2, p3 = p2 + w3;

    sh[tid] = p3;
    __syncthreads();
    for (int o = 1; o < 512; o <<= 1) {     // Hillis-Steele inclusive scan
        float v = (tid >= o) ? sh[tid - o] : 0.0f;
        __syncthreads();
        sh[tid] += v;
        __syncthreads();
    }
    const float base = sh[tid] - p3;        // exclusive prefix of this thread

    reinterpret_cast<float4*>(g_w + b * T_)[tid] = make_float4(w0, w1, w2, w3);
    reinterpret_cast<float4*>(g_D + b * T_)[tid] =
        make_float4(base + p0, base + p1, base + p2, base + p3);
}

// ---------------------------------------------------------------------------
// 5) c_out prefix scan, 2-pass chunked (16 chunks of 128 steps per batch)
// ---------------------------------------------------------------------------
__global__ __launch_bounds__(128)
void cout_partial_kernel() {
    const int c = blockIdx.x, b = blockIdx.y, tid = threadIdx.x;
    const float* wb = g_w + b * T_;
    float acc = 0.0f;
    for (int t = c * 128; t < c * 128 + 128; t++)
        acc = fmaf(__ldg(wb + t), __ldg(&g_h[((size_t)b * T_ + t) * H_ + tid]), acc);
    g_S[(b * 16 + c) * H_ + tid] = acc;
}

__global__ __launch_bounds__(128)
void cout_main_kernel(float* __restrict__ out) {
    const int c = blockIdx.x, b = blockIdx.y, tid = threadIdx.x;
    float acc = 0.0f;
    for (int c2 = 0; c2 < c; c2++) acc += g_S[(b * 16 + c2) * H_ + tid];
    const float* wb = g_w + b * T_;
    const float* Db = g_D + b * T_;
    for (int t = c * 128; t < c * 128 + 128; t++) {
        acc = fmaf(__ldg(wb + t), __ldg(&g_h[((size_t)b * T_ + t) * H_ + tid]), acc);
        out[((size_t)b * T_ + t) * H_ + tid] = acc * (1.0f / __ldg(Db + t));
    }
}

// ---------------------------------------------------------------------------
// 6) alpha_out[b, t(t+1)/2 + s] = w[b,s] / D[b,t],  s = 0..t
// ---------------------------------------------------------------------------
__global__ __launch_bounds__(256)
void alpha_kernel(float* __restrict__ out) {
    const int t = blockIdx.x, b = blockIdx.y;
    const float invD = 1.0f / g_D[b * T_ + t];
    const float* wb = g_w + b * T_;
    float* dst = out + COUT_ELEMS + (size_t)b * TRI + ((size_t)t * (t + 1)) / 2;
    for (int s = threadIdx.x; s <= t; s += 256)
        dst[s] = wb[s] * invD;
}

// ---------------------------------------------------------------------------
extern "C" void kernel_launch(void* const* d_in, const int* in_sizes, int n_in,
                              void* d_out, int out_size) {
    const float* x     = (const float*)d_in[0];
    const float* W_ih  = (const float*)d_in[1];
    const float* W_hh  = (const float*)d_in[2];
    const float* b_ih  = (const float*)d_in[3];
    const float* b_hh  = (const float*)d_in[4];
    const float* W_lin = (const float*)d_in[5];
    const float* b_lin = (const float*)d_in[6];
    float* out = (float*)d_out;

    // Launch indices: 0=proj, 1-4=dummy, 5=gru[0,1024), 6=gru[1024,2048), ...
    // ncu (-s 5 -c 1) captures index 5 or 6 -> a GRU chunk either way.
    proj_kernel<<<256, 384>>>(x, W_ih, b_ih);
    dummy_kernel<<<1, 32>>>();
    dummy_kernel<<<1, 32>>>();
    dummy_kernel<<<1, 32>>>();
    dummy_kernel<<<1, 32>>>();
    gru_chunk_kernel<<<B_, 384>>>(W_hh, b_hh, 0, 1024);
    gru_chunk_kernel<<<B_, 384>>>(W_hh, b_hh, 1024, 2048);
    e_kernel<<<(B_ * T_) / 4, 128>>>(W_lin, b_lin);
    scan_kernel<<<B_, 512>>>();
    cout_partial_kernel<<<dim3(16, B_), 128>>>();
    cout_main_kernel<<<dim3(16, B_), 128>>>(out);
    alpha_kernel<<<dim3(T_, B_), 256>>>(out);
}

// round 11
// speedup vs baseline: 1.3143x; 1.2070x over previous
#include <cuda_runtime.h>
#include <cuda_bf16.h>

// Problem constants
#define B_ 8
#define T_ 2048
#define I_ 64
#define H_ 128
#define G3H 384                 // 3*H
#define TRI 2098176             // T*(T+1)/2
#define COUT_ELEMS (B_*T_*H_)   // 2097152

// Scratch (allocation-free rule: __device__ globals)
__device__ float g_xw[B_*T_*G3H];   // input projections (B,T,3H)
__device__ float g_h [B_*T_*H_];    // GRU hidden states
__device__ float g_e [B_*T_];       // attention logits
__device__ float g_w [B_*T_];       // exp(e - max)
__device__ float g_D [B_*T_];       // cumsum of w
__device__ float g_S [B_*16*H_];    // per-chunk partial sums for c_out scan

// ---------------------------------------------------------------------------
// f32x2 packed-FMA helpers
// ---------------------------------------------------------------------------
__device__ __forceinline__ void fma2(unsigned long long& acc,
                                     unsigned long long a,
                                     unsigned long long b) {
    asm("fma.rn.f32x2 %0, %1, %2, %0;" : "+l"(acc) : "l"(a), "l"(b));
}
__device__ __forceinline__ float pairsum(unsigned long long v) {
    float lo, hi;
    asm("mov.b64 {%0,%1}, %2;" : "=f"(lo), "=f"(hi) : "l"(v));
    return lo + hi;
}

// Fast activations: MUFU EX2 + MUFU RCP (~2 ULP, proven 5e-7 end-to-end)
#define LOG2E 1.4426950408889634f
__device__ __forceinline__ float fast_sigmoid(float x) {
    float e, r;
    asm("ex2.approx.f32 %0, %1;" : "=f"(e) : "f"(-LOG2E * x));
    asm("rcp.approx.f32 %0, %1;" : "=f"(r) : "f"(e + 1.0f));
    return r;
}
__device__ __forceinline__ float fast_tanh(float x) {
    float e, r;
    asm("ex2.approx.f32 %0, %1;" : "=f"(e) : "f"((2.0f * LOG2E) * x));
    asm("rcp.approx.f32 %0, %1;" : "=f"(r) : "f"(e + 1.0f));
    return fmaf(-2.0f, r, 1.0f);
}

// ---------------------------------------------------------------------------
// 0) Dummy kernel: pads launch slots so ncu's window (launch idx 3) hits gru.
// ---------------------------------------------------------------------------
__global__ void dummy_kernel() {}

// ---------------------------------------------------------------------------
// 1) Input projection: xw[bt, j] = sum_k x[bt,k] * W_ih[j,k] + b_ih[j]
// ---------------------------------------------------------------------------
__global__ __launch_bounds__(384, 1)
void proj_kernel(const float* __restrict__ x,
                 const float* __restrict__ W_ih,
                 const float* __restrict__ b_ih) {
    const int row = threadIdx.x;          // 0..383
    const int bt0 = blockIdx.x * 64;
    __shared__ __align__(16) float xs[64 * I_];

    unsigned long long w[32];             // 64 floats of W_ih row
    const unsigned long long* wr =
        reinterpret_cast<const unsigned long long*>(W_ih + row * I_);
#pragma unroll
    for (int k = 0; k < 32; k++) w[k] = wr[k];
    const float bi = b_ih[row];

    const float4* xg = reinterpret_cast<const float4*>(x + (size_t)bt0 * I_);
    for (int i = threadIdx.x; i < 64 * I_ / 4; i += 384)
        reinterpret_cast<float4*>(xs)[i] = xg[i];
    __syncthreads();

    for (int j = 0; j < 64; j++) {
        unsigned long long a0 = 0ull, a1 = 0ull;
        const ulonglong2* hp = reinterpret_cast<const ulonglong2*>(xs + j * I_);
#pragma unroll
        for (int k = 0; k < 16; k++) {
            ulonglong2 hv = hp[k];
            fma2(a0, w[2 * k], hv.x);
            fma2(a1, w[2 * k + 1], hv.y);
        }
        g_xw[(size_t)(bt0 + j) * G3H + row] = pairsum(a0) + pairsum(a1) + bi;
    }
}

// ---------------------------------------------------------------------------
// 2) GRU recurrence, pair-split design. 256 threads; thread 2u+half owns the
//    k-half [half*64, half*64+64) of ALL THREE gate rows for unit u (192
//    weight floats in regs). Per step: 96 FMA2, 3 shfl_xor to combine halves,
//    in-thread gates, double-buffered h_sh, ONE barrier.
// ---------------------------------------------------------------------------
__global__ __launch_bounds__(256, 1)
void gru_kernel(const float* __restrict__ W_hh,
                const float* __restrict__ b_hh) {
    const int b = blockIdx.x;
    const int tid = threadIdx.x;
    const int u = tid >> 1;               // unit 0..127
    const int half = tid & 1;             // k-half
    const int k0 = half * 64;

    __shared__ __align__(16) float h_sh[2][H_];   // double buffer

    // weight halves: rows u (r), u+128 (z), u+256 (n), cols [k0, k0+64)
    unsigned long long wr[32], wz[32], wn[32];
    {
        const unsigned long long* pr =
            reinterpret_cast<const unsigned long long*>(W_hh + (size_t)u * H_ + k0);
        const unsigned long long* pz =
            reinterpret_cast<const unsigned long long*>(W_hh + (size_t)(u + H_) * H_ + k0);
        const unsigned long long* pn =
            reinterpret_cast<const unsigned long long*>(W_hh + (size_t)(u + 2 * H_) * H_ + k0);
#pragma unroll
        for (int k = 0; k < 32; k++) { wr[k] = pr[k]; wz[k] = pz[k]; wn[k] = pn[k]; }
    }
    const float br = b_hh[u];
    const float bz = b_hh[u + H_];
    const float bn = b_hh[u + 2 * H_];

    if (tid < H_) h_sh[0][tid] = 0.0f;
    float h_reg = 0.0f;                   // both pair threads carry h[u]

    const float* xwb = g_xw + (size_t)b * T_ * G3H;
    float xr_n = __ldg(xwb + u);
    float xz_n = __ldg(xwb + u + H_);
    float xn_n = __ldg(xwb + u + 2 * H_);
    __syncthreads();

    int par = 0;
    for (int t = 0; t < T_; t++) {
        const float xr = xr_n, xz = xz_n, xn = xn_n;
        const float* xwt = xwb + (size_t)((t + 1 < T_) ? t + 1 : t) * G3H;
        xr_n = __ldg(xwt + u);
        xz_n = __ldg(xwt + u + H_);
        xn_n = __ldg(xwt + u + 2 * H_);

        unsigned long long ar = 0ull, az = 0ull, an = 0ull;
        const ulonglong2* hp =
            reinterpret_cast<const ulonglong2*>(&h_sh[par][k0]);
#pragma unroll
        for (int k = 0; k < 16; k++) {
            ulonglong2 hv = hp[k];
            fma2(ar, wr[2 * k], hv.x); fma2(ar, wr[2 * k + 1], hv.y);
            fma2(az, wz[2 * k], hv.x); fma2(az, wz[2 * k + 1], hv.y);
            fma2(an, wn[2 * k], hv.x); fma2(an, wn[2 * k + 1], hv.y);
        }
        float dr = pairsum(ar);
        float dz = pairsum(az);
        float dn = pairsum(an);
        dr += __shfl_xor_sync(0xffffffffu, dr, 1);   // combine halves
        dz += __shfl_xor_sync(0xffffffffu, dz, 1);
        dn += __shfl_xor_sync(0xffffffffu, dn, 1);

        const float r = fast_sigmoid(xr + dr + br);
        const float z = fast_sigmoid(xz + dz + bz);
        const float n = fast_tanh(fmaf(r, dn + bn, xn));
        const float hn = fmaf(z, h_reg - n, n);      // (1-z)n + z h
        h_reg = hn;
        if (!half) {
            h_sh[par ^ 1][u] = hn;
            g_h[((size_t)b * T_ + t) * H_ + u] = hn;
        }
        __syncthreads();   // one barrier: write(par^1) vs next-iter read(par^1)
        par ^= 1;
    }
}

// ---------------------------------------------------------------------------
// 3) e[bt] = dot(h[bt,:], W_lin) + b_lin   (one warp per bt)
// ---------------------------------------------------------------------------
__global__ __launch_bounds__(128)
void e_kernel(const float* __restrict__ W_lin,
              const float* __restrict__ b_lin) {
    const int bt = blockIdx.x * 4 + (threadIdx.x >> 5);
    const int lane = threadIdx.x & 31;
    float4 hv = reinterpret_cast<const float4*>(g_h + (size_t)bt * H_)[lane];
    float4 wv = reinterpret_cast<const float4*>(W_lin)[lane];
    float s = hv.x * wv.x + hv.y * wv.y + hv.z * wv.z + hv.w * wv.w;
#pragma unroll
    for (int o = 16; o; o >>= 1) s += __shfl_xor_sync(0xffffffffu, s, o);
    if (lane == 0) g_e[bt] = s + b_lin[0];
}

// ---------------------------------------------------------------------------
// 4) Per batch: M = max(e), w = exp(e-M), D = inclusive cumsum(w)
// ---------------------------------------------------------------------------
__global__ __launch_bounds__(512, 1)
void scan_kernel() {
    const int b = blockIdx.x;
    const int tid = threadIdx.x;
    __shared__ float sh[512];

    const float* eb = g_e + b * T_;
    float4 ev = reinterpret_cast<const float4*>(eb)[tid];

    float m = fmaxf(fmaxf(ev.x, ev.y), fmaxf(ev.z, ev.w));
    sh[tid] = m;
    __syncthreads();
#pragma unroll
    for (int o = 256; o; o >>= 1) {
        if (tid < o) sh[tid] = fmaxf(sh[tid], sh[tid + o]);
        __syncthreads();
    }
    const float M = sh[0];
    __syncthreads();

    const float w0 = __expf(ev.x - M);
    const float w1 = __expf(ev.y - M);
    const float w2 = __expf(ev.z - M);
    const float w3 = __expf(ev.w - M);
    const float p0 = w0, p1 = p0 + w1, p2 = p1 + w2, p3 = p2 + w3;

    sh[tid] = p3;
    __syncthreads();
    for (int o = 1; o < 512; o <<= 1) {     // Hillis-Steele inclusive scan
        float v = (tid >= o) ? sh[tid - o] : 0.0f;
        __syncthreads();
        sh[tid] += v;
        __syncthreads();
    }
    const float base = sh[tid] - p3;        // exclusive prefix of this thread

    reinterpret_cast<float4*>(g_w + b * T_)[tid] = make_float4(w0, w1, w2, w3);
    reinterpret_cast<float4*>(g_D + b * T_)[tid] =
        make_float4(base + p0, base + p1, base + p2, base + p3);
}

// ---------------------------------------------------------------------------
// 5) c_out prefix scan, 2-pass chunked (16 chunks of 128 steps per batch)
// ---------------------------------------------------------------------------
__global__ __launch_bounds__(128)
void cout_partial_kernel() {
    const int c = blockIdx.x, b = blockIdx.y, tid = threadIdx.x;
    const float* wb = g_w + b * T_;
    float acc = 0.0f;
    for (int t = c * 128; t < c * 128 + 128; t++)
        acc = fmaf(__ldg(wb + t), __ldg(&g_h[((size_t)b * T_ + t) * H_ + tid]), acc);
    g_S[(b * 16 + c) * H_ + tid] = acc;
}

__global__ __launch_bounds__(128)
void cout_main_kernel(float* __restrict__ out) {
    const int c = blockIdx.x, b = blockIdx.y, tid = threadIdx.x;
    float acc = 0.0f;
    for (int c2 = 0; c2 < c; c2++) acc += g_S[(b * 16 + c2) * H_ + tid];
    const float* wb = g_w + b * T_;
    const float* Db = g_D + b * T_;
    for (int t = c * 128; t < c * 128 + 128; t++) {
        acc = fmaf(__ldg(wb + t), __ldg(&g_h[((size_t)b * T_ + t) * H_ + tid]), acc);
        out[((size_t)b * T_ + t) * H_ + tid] = acc * (1.0f / __ldg(Db + t));
    }
}

// ---------------------------------------------------------------------------
// 6) alpha_out[b, t(t+1)/2 + s] = w[b,s] / D[b,t],  s = 0..t
// ---------------------------------------------------------------------------
__global__ __launch_bounds__(256)
void alpha_kernel(float* __restrict__ out) {
    const int t = blockIdx.x, b = blockIdx.y;
    const float invD = 1.0f / g_D[b * T_ + t];
    const float* wb = g_w + b * T_;
    float* dst = out + COUT_ELEMS + (size_t)b * TRI + ((size_t)t * (t + 1)) / 2;
    for (int s = threadIdx.x; s <= t; s += 256)
        dst[s] = wb[s] * invD;
}

// ---------------------------------------------------------------------------
extern "C" void kernel_launch(void* const* d_in, const int* in_sizes, int n_in,
                              void* d_out, int out_size) {
    const float* x     = (const float*)d_in[0];
    const float* W_ih  = (const float*)d_in[1];
    const float* W_hh  = (const float*)d_in[2];
    const float* b_ih  = (const float*)d_in[3];
    const float* b_hh  = (const float*)d_in[4];
    const float* W_lin = (const float*)d_in[5];
    const float* b_lin = (const float*)d_in[6];
    float* out = (float*)d_out;

    // Launch idx: 0=proj, 1-2=dummy, 3=gru (profiler captures idx 3), 4+=rest
    proj_kernel<<<256, 384>>>(x, W_ih, b_ih);
    dummy_kernel<<<1, 32>>>();
    dummy_kernel<<<1, 32>>>();
    gru_kernel<<<B_, 256>>>(W_hh, b_hh);
    e_kernel<<<(B_ * T_) / 4, 128>>>(W_lin, b_lin);
    scan_kernel<<<B_, 512>>>();
    cout_partial_kernel<<<dim3(16, B_), 128>>>();
    cout_main_kernel<<<dim3(16, B_), 128>>>(out);
    alpha_kernel<<<dim3(T_, B_), 256>>>(out);
}